// round 1
// baseline (speedup 1.0000x reference)
#include <cuda_runtime.h>
#include <math.h>

#define NVOX 65536            // 64*64*16 voxels
#define CCH 64
#define NHEAD 8
#define DHEAD 8

// ---------------- scratch (device globals; no allocation allowed) ----------
__device__ float f_xu[CCH * NVOX];   // upsampled x, channel-first [c][v]
__device__ float f_q[NVOX * CCH];    // q projection, channel-last [v][c]
__device__ float f_k[NVOX * CCH];
__device__ float f_v[NVOX * CCH];
__device__ float f_o[NVOX * CCH];    // attention output pre-Wo
__device__ float g_sum[128], g_sumsq[128];     // [0:64] xu stats, [64:128] skip stats
__device__ float g_Wq[CCH * CCH], g_Wk[CCH * CCH], g_Wv[CCH * CCH];
__device__ float g_bq[CCH], g_bk[CCH], g_bv[CCH];

// ---------------- 1) trilinear upsample x(64,32,32,8) -> f_xu(64,64,64,16) --
__global__ __launch_bounds__(256) void upsample_kernel(const float* __restrict__ x) {
    int v = blockIdx.x * 256 + threadIdx.x;
    int h = v >> 10;
    int w = (v >> 4) & 63;
    int z = v & 15;

    const float rh = (float)(31.0 / 63.0);
    const float rw = (float)(31.0 / 63.0);
    const float rz = (float)(7.0 / 15.0);

    float ph = (float)h * rh; int ih = (int)ph; if (ih > 30) ih = 30; float fh = ph - (float)ih;
    float pw = (float)w * rw; int iw = (int)pw; if (iw > 30) iw = 30; float fw = pw - (float)iw;
    float pz = (float)z * rz; int iz = (int)pz; if (iz > 6)  iz = 6;  float fz = pz - (float)iz;

    int base = ih * 256 + iw * 8 + iz;   // strides: h=256, w=8, z=1

#pragma unroll 8
    for (int c = 0; c < CCH; c++) {
        const float* xc = x + c * 8192 + base;
        float c000 = xc[0],   c100 = xc[256], c010 = xc[8],   c110 = xc[264];
        float c001 = xc[1],   c101 = xc[257], c011 = xc[9],   c111 = xc[265];
        // interp H, then W, then Z (matches reference order)
        float a00 = c000 + fh * (c100 - c000);
        float a10 = c010 + fh * (c110 - c010);
        float a01 = c001 + fh * (c101 - c001);
        float a11 = c011 + fh * (c111 - c011);
        float b0  = a00 + fw * (a10 - a00);
        float b1  = a01 + fw * (a11 - a01);
        f_xu[c * NVOX + v] = b0 + fz * (b1 - b0);
    }
}

// ---------------- 2) per-channel sum / sumsq for xu and skip ----------------
__global__ __launch_bounds__(256) void stats_kernel(const float* __restrict__ skip) {
    int b = blockIdx.x;   // 0..127
    const float* p = (b < 64) ? (f_xu + b * NVOX) : (skip + (b - 64) * NVOX);
    float s = 0.f, s2 = 0.f;
    for (int i = threadIdx.x; i < NVOX; i += 256) {
        float val = p[i];
        s += val; s2 += val * val;
    }
    __shared__ float sh1[256], sh2[256];
    sh1[threadIdx.x] = s; sh2[threadIdx.x] = s2;
    __syncthreads();
    for (int off = 128; off > 0; off >>= 1) {
        if (threadIdx.x < off) {
            sh1[threadIdx.x] += sh1[threadIdx.x + off];
            sh2[threadIdx.x] += sh2[threadIdx.x + off];
        }
        __syncthreads();
    }
    if (threadIdx.x == 0) { g_sum[b] = sh1[0]; g_sumsq[b] = sh2[0]; }
}

// ---------------- 3) fold instance-norm (+ q scale) into weights -----------
__global__ void fold_kernel(const float* __restrict__ Wq, const float* __restrict__ bq,
                            const float* __restrict__ Wk, const float* __restrict__ bk,
                            const float* __restrict__ Wv, const float* __restrict__ bv) {
    __shared__ float skv[64], okv[64], sq_[64], oq_[64];
    int t = threadIdx.x;    // 64 threads
    const float invN = 1.0f / 65536.0f;
    float m  = g_sum[t] * invN;
    float va = g_sumsq[t] * invN - m * m;
    float sc = rsqrtf(va + 1e-5f);
    skv[t] = sc; okv[t] = -m * sc;
    m  = g_sum[64 + t] * invN;
    va = g_sumsq[64 + t] * invN - m * m;
    sc = rsqrtf(va + 1e-5f);
    sq_[t] = sc; oq_[t] = -m * sc;
    __syncthreads();

    const float scale = 0.3535533905932738f;  // dh^-0.5, dh=8
    float aq = 0.f, ak = 0.f, av = 0.f;
    for (int c = 0; c < 64; c++) {
        float wq = Wq[c * 64 + t]; g_Wq[c * 64 + t] = wq * sq_[c] * scale; aq += oq_[c] * wq;
        float wk = Wk[c * 64 + t]; g_Wk[c * 64 + t] = wk * skv[c];          ak += okv[c] * wk;
        float wv = Wv[c * 64 + t]; g_Wv[c * 64 + t] = wv * skv[c];          av += okv[c] * wv;
    }
    g_bq[t] = scale * (bq[t] + aq);
    g_bk[t] = bk[t] + ak;
    g_bv[t] = bv[t] + av;
}

// ---------------- 4) q projection: raw skip -> f_q (norm folded) -----------
__global__ __launch_bounds__(256) void projq_kernel(const float* __restrict__ skip) {
    __shared__ float sW[4096];
    __shared__ float sb[64];
    int tid = threadIdx.x;
    for (int i = tid; i < 4096; i += 256) sW[i] = g_Wq[i];
    if (tid < 64) sb[tid] = g_bq[tid];
    __syncthreads();

    int v = blockIdx.x * 256 + tid;
    float in_r[64];
#pragma unroll
    for (int c = 0; c < 64; c++) in_r[c] = skip[c * NVOX + v];

#pragma unroll
    for (int j0 = 0; j0 < 64; j0 += 4) {
        float4 acc = *(const float4*)&sb[j0];
#pragma unroll
        for (int c = 0; c < 64; c++) {
            float4 wv4 = *(const float4*)&sW[c * 64 + j0];
            acc.x = fmaf(in_r[c], wv4.x, acc.x);
            acc.y = fmaf(in_r[c], wv4.y, acc.y);
            acc.z = fmaf(in_r[c], wv4.z, acc.z);
            acc.w = fmaf(in_r[c], wv4.w, acc.w);
        }
        *(float4*)&f_q[v * 64 + j0] = acc;
    }
}

// ---------------- 5) k,v projection: f_xu -> f_k, f_v ----------------------
__global__ __launch_bounds__(256) void projkv_kernel() {
    __shared__ float sWk[4096], sWv[4096];
    __shared__ float sbk[64], sbv[64];
    int tid = threadIdx.x;
    for (int i = tid; i < 4096; i += 256) { sWk[i] = g_Wk[i]; sWv[i] = g_Wv[i]; }
    if (tid < 64) { sbk[tid] = g_bk[tid]; sbv[tid] = g_bv[tid]; }
    __syncthreads();

    int v = blockIdx.x * 256 + tid;
    float in_r[64];
#pragma unroll
    for (int c = 0; c < 64; c++) in_r[c] = f_xu[c * NVOX + v];

#pragma unroll
    for (int j0 = 0; j0 < 64; j0 += 4) {
        float4 acc = *(const float4*)&sbk[j0];
#pragma unroll
        for (int c = 0; c < 64; c++) {
            float4 wv4 = *(const float4*)&sWk[c * 64 + j0];
            acc.x = fmaf(in_r[c], wv4.x, acc.x);
            acc.y = fmaf(in_r[c], wv4.y, acc.y);
            acc.z = fmaf(in_r[c], wv4.z, acc.z);
            acc.w = fmaf(in_r[c], wv4.w, acc.w);
        }
        *(float4*)&f_k[v * 64 + j0] = acc;
    }
#pragma unroll
    for (int j0 = 0; j0 < 64; j0 += 4) {
        float4 acc = *(const float4*)&sbv[j0];
#pragma unroll
        for (int c = 0; c < 64; c++) {
            float4 wv4 = *(const float4*)&sWv[c * 64 + j0];
            acc.x = fmaf(in_r[c], wv4.x, acc.x);
            acc.y = fmaf(in_r[c], wv4.y, acc.y);
            acc.z = fmaf(in_r[c], wv4.z, acc.z);
            acc.w = fmaf(in_r[c], wv4.w, acc.w);
        }
        *(float4*)&f_v[v * 64 + j0] = acc;
    }
}

// ---------------- 6) tiled neighborhood attention --------------------------
// tile 8x8x4 voxels, halo 10x10x6 = 600, one block per (tile, head)
__global__ __launch_bounds__(256) void attn_kernel(const float* __restrict__ rpb) {
    __shared__ float4 ks4[600 * 2];
    __shared__ float4 vs4[600 * 2];
    __shared__ float bias_s[125];

    int tid  = threadIdx.x;
    int tb   = blockIdx.x;          // 0..255 : 8x8x4 tiles
    int head = blockIdx.y;
    int h0 = (tb >> 5) * 8;
    int w0 = ((tb >> 2) & 7) * 8;
    int z0 = (tb & 3) * 4;

    for (int i = tid; i < 600; i += 256) {
        int ah = i / 60; int r = i - ah * 60; int aw = r / 6; int az = r - aw * 6;
        int gh = min(max(h0 - 1 + ah, 0), 63);
        int gw = min(max(w0 - 1 + aw, 0), 63);
        int gz = min(max(z0 - 1 + az, 0), 15);
        int gv = ((gh << 6) + gw) * 16 + gz;
        const float4* pk = (const float4*)(f_k + gv * 64 + head * 8);
        ks4[i * 2]     = pk[0];
        ks4[i * 2 + 1] = pk[1];
        const float4* pv = (const float4*)(f_v + gv * 64 + head * 8);
        vs4[i * 2]     = pv[0];
        vs4[i * 2 + 1] = pv[1];
    }
    if (tid < 125) bias_s[tid] = rpb[head * 125 + tid];
    __syncthreads();

    int lth = tid >> 5;
    int ltw = (tid >> 2) & 7;
    int ltz = tid & 3;
    int h = h0 + lth, w = w0 + ltw, z = z0 + ltz;
    int v = ((h << 6) + w) * 16 + z;

    const float4* pq = (const float4*)(f_q + v * 64 + head * 8);
    float4 q0 = pq[0], q1 = pq[1];

    int sh = min(max(h - 1, 0), 61);
    int sw = min(max(w - 1, 0), 61);
    int sz = min(max(z - 1, 0), 13);
    int lhh = sh - h0 + 1, lww = sw - w0 + 1, lzz = sz - z0 + 1;
    int rb = (sh - h + 2) * 25 + (sw - w + 2) * 5 + (sz - z + 2);

    float logits[27];
    int   hls[27];
    float mx = -1e30f;
#pragma unroll
    for (int a = 0; a < 3; a++)
#pragma unroll
    for (int b = 0; b < 3; b++)
#pragma unroll
    for (int cc = 0; cc < 3; cc++) {
        int m  = (a * 3 + b) * 3 + cc;
        int hl = ((lhh + a) * 10 + (lww + b)) * 6 + (lzz + cc);
        hls[m] = hl;
        float4 ka = ks4[hl * 2], kb = ks4[hl * 2 + 1];
        float d = q0.x * ka.x + q0.y * ka.y + q0.z * ka.z + q0.w * ka.w
                + q1.x * kb.x + q1.y * kb.y + q1.z * kb.z + q1.w * kb.w;
        d += bias_s[rb + a * 25 + b * 5 + cc];
        logits[m] = d;
        mx = fmaxf(mx, d);
    }
    float ssum = 0.f;
#pragma unroll
    for (int m = 0; m < 27; m++) {
        float e = __expf(logits[m] - mx);
        logits[m] = e;
        ssum += e;
    }
    float inv = 1.0f / ssum;
    float4 o0 = make_float4(0.f, 0.f, 0.f, 0.f);
    float4 o1 = make_float4(0.f, 0.f, 0.f, 0.f);
#pragma unroll
    for (int m = 0; m < 27; m++) {
        float a_ = logits[m] * inv;
        float4 va = vs4[hls[m] * 2], vb = vs4[hls[m] * 2 + 1];
        o0.x = fmaf(a_, va.x, o0.x); o0.y = fmaf(a_, va.y, o0.y);
        o0.z = fmaf(a_, va.z, o0.z); o0.w = fmaf(a_, va.w, o0.w);
        o1.x = fmaf(a_, vb.x, o1.x); o1.y = fmaf(a_, vb.y, o1.y);
        o1.z = fmaf(a_, vb.z, o1.z); o1.w = fmaf(a_, vb.w, o1.w);
    }
    float4* po = (float4*)(f_o + v * 64 + head * 8);
    po[0] = o0;
    po[1] = o1;
}

// ---------------- 7) output projection f_o @ Wo + bo -> channel-first out ---
__global__ __launch_bounds__(256) void oproj_kernel(const float* __restrict__ Wo,
                                                    const float* __restrict__ bo,
                                                    float* __restrict__ out) {
    __shared__ float sW[4096];
    __shared__ float sb[64];
    int tid = threadIdx.x;
    for (int i = tid; i < 4096; i += 256) sW[i] = Wo[i];
    if (tid < 64) sb[tid] = bo[tid];
    __syncthreads();

    int v = blockIdx.x * 256 + tid;
    float in_r[64];
#pragma unroll
    for (int c4 = 0; c4 < 16; c4++) {
        float4 t = ((const float4*)(f_o + v * 64))[c4];
        in_r[c4 * 4 + 0] = t.x;
        in_r[c4 * 4 + 1] = t.y;
        in_r[c4 * 4 + 2] = t.z;
        in_r[c4 * 4 + 3] = t.w;
    }

#pragma unroll
    for (int j0 = 0; j0 < 64; j0 += 4) {
        float4 acc = *(const float4*)&sb[j0];
#pragma unroll
        for (int c = 0; c < 64; c++) {
            float4 wv4 = *(const float4*)&sW[c * 64 + j0];
            acc.x = fmaf(in_r[c], wv4.x, acc.x);
            acc.y = fmaf(in_r[c], wv4.y, acc.y);
            acc.z = fmaf(in_r[c], wv4.z, acc.z);
            acc.w = fmaf(in_r[c], wv4.w, acc.w);
        }
        out[(j0 + 0) * NVOX + v] = acc.x;
        out[(j0 + 1) * NVOX + v] = acc.y;
        out[(j0 + 2) * NVOX + v] = acc.z;
        out[(j0 + 3) * NVOX + v] = acc.w;
    }
}

// ---------------------------------------------------------------------------
extern "C" void kernel_launch(void* const* d_in, const int* in_sizes, int n_in,
                              void* d_out, int out_size) {
    const float* x    = (const float*)d_in[0];
    const float* skip = (const float*)d_in[1];
    const float* Wq   = (const float*)d_in[2];
    const float* bq   = (const float*)d_in[3];
    const float* Wk   = (const float*)d_in[4];
    const float* bk   = (const float*)d_in[5];
    const float* Wv   = (const float*)d_in[6];
    const float* bv   = (const float*)d_in[7];
    const float* Wo   = (const float*)d_in[8];
    const float* bo   = (const float*)d_in[9];
    const float* rpb  = (const float*)d_in[10];
    float* out = (float*)d_out;

    upsample_kernel<<<256, 256>>>(x);
    stats_kernel<<<128, 256>>>(skip);
    fold_kernel<<<1, 64>>>(Wq, bq, Wk, bk, Wv, bv);
    projq_kernel<<<256, 256>>>(skip);
    projkv_kernel<<<256, 256>>>();
    attn_kernel<<<dim3(256, 8), 256>>>(rpb);
    oproj_kernel<<<256, 256>>>(Wo, bo, out);
}